// round 16
// baseline (speedup 1.0000x reference)
#include <cuda_runtime.h>
#include <math.h>

#define NSP 9216        // 16*24*24
#define DD 16
#define HH 24
#define WW 24
#define PROW 26         // padded row (W+2)
#define PPLN 676        // padded plane (H+2)*(W+2)
#define PCH  12168      // padded channel (D+2)*PPLN
#define KS 16           // key splits for attention
#define KPS (NSP / KS)  // 576 keys per split
#define ESHIFT 40.0f    // fixed softmax shift
#define LOG2E 1.4426950408889634f
#define E2 (ESHIFT * LOG2E)
#define HALO 234        // 3d * 3h * 26w halo positions per (d,h) row tile

typedef unsigned long long ull;

// ---------------- f32x2 packed helpers (sm_100+) ---------------------------
__device__ __forceinline__ ull pack2(float lo, float hi) {
    ull r;
    asm("mov.b64 %0, {%1, %2};" : "=l"(r) : "f"(lo), "f"(hi));
    return r;
}
__device__ __forceinline__ float2 unpack2(ull v) {
    float2 f;
    asm("mov.b64 {%0, %1}, %2;" : "=f"(f.x), "=f"(f.y) : "l"(v));
    return f;
}
__device__ __forceinline__ void fma2(ull& d, ull a, ull b) {
    asm("fma.rn.f32x2 %0, %1, %2, %3;" : "=l"(d) : "l"(a), "l"(b), "l"(d));
}
__device__ __forceinline__ unsigned f2tf32(float f) {
    unsigned u;
    asm("cvt.rna.tf32.f32 %0, %1;" : "=r"(u) : "f"(f));
    return u;
}
__device__ __forceinline__ float ex2(float x) {
    float r;
    asm("ex2.approx.f32 %0, %1;" : "=f"(r) : "f"(x));
    return r;
}
// D += A(16x8) @ B(8x8), tf32 inputs, f32 accum (m16n8k8 row.col)
__device__ __forceinline__ void mma_tf32(float* d,
    unsigned a0, unsigned a1, unsigned a2, unsigned a3,
    unsigned b0, unsigned b1) {
    asm("mma.sync.aligned.m16n8k8.row.col.f32.tf32.tf32.f32 "
        "{%0,%1,%2,%3}, {%4,%5,%6,%7}, {%8,%9}, {%0,%1,%2,%3};"
        : "+f"(d[0]), "+f"(d[1]), "+f"(d[2]), "+f"(d[3])
        : "r"(a0), "r"(a1), "r"(a2), "r"(a3), "r"(b0), "r"(b1));
}

// ---------------- scratch (device globals; zero-initialized) ---------------
__device__ __align__(16) float d_xpad[64 * PCH];      // padded x (borders 0)
__device__ __align__(16) float d_ogpad[32 * PCH];     // padded attn out
__device__ __align__(16) float d_theta[NSP * 8];      // [n][c]
__device__ __align__(16) float d_phi[NSP * 8];        // [n][c]
__device__ __align__(16) float d_g[NSP * 32];         // [n][c]
__device__ __align__(16) float d_pl[KS * NSP];        // partial sum
__device__ __align__(16) float d_pacc[KS * NSP * 32]; // partial acc
__device__ __align__(16) float d_y[64 * NSP];         // o-conv out, [c][n]

// tap offsets into padded layout (compile-time immediates after unroll)
#define TAPOFF(t) ((t / 9) * PPLN + ((t / 3) % 3) * PROW + (t % 3))

// ---------------- kernel 0: pad x into halo layout -------------------------
__global__ __launch_bounds__(256) void pad_x(const float* __restrict__ x)
{
    const int idx = blockIdx.x * 256 + threadIdx.x;
    if (idx >= 64 * NSP) return;
    const int c = idx / NSP, n = idx % NSP;
    const int d = n / (HH * WW), r = n % (HH * WW);
    const int h = r / WW, w = r % WW;
    d_xpad[c * PCH + (d + 1) * PPLN + (h + 1) * PROW + (w + 1)] = x[idx];
}

// ---------------- kernel 1a: theta/phi conv3d (scalar fp32, logit path) ----
// grid: (96, 2) — 96 spatial tiles (1x4x24); gy=0 theta, gy=1 phi
__global__ __launch_bounds__(96) void conv_thph(
    const float* __restrict__ tw, const float* __restrict__ tb,
    const float* __restrict__ pw, const float* __restrict__ pb)
{
    __shared__ __align__(16) float ws[16 * 27 * 8];   // [ci][tap][co]

    const int tid = threadIdx.x;
    const int gy = blockIdx.y;
    const int d = blockIdx.x / 6;
    const int h = (blockIdx.x % 6) * 4 + tid / 24;
    const int w = tid % 24;
    const int corner = d * PPLN + h * PROW + w;

    ull acc2[4];
#pragma unroll
    for (int j = 0; j < 4; j++) acc2[j] = 0ull;

    for (int cc = 0; cc < 4; cc++) {          // ci chunks of 16
        for (int i = tid; i < 16 * 27 * 8; i += 96) {
            const int ci  = i / (27 * 8);
            const int rem = i % (27 * 8);
            const int tap = rem / 8;
            const int co  = rem % 8;
            const int cig = cc * 16 + ci;
            ws[(ci * 27 + tap) * 8 + co] =
                gy == 0 ? tw[(co * 64 + cig) * 27 + tap]
                        : pw[(co * 64 + cig) * 27 + tap];
        }
        __syncthreads();

        for (int ci = 0; ci < 16; ci++) {
            const float* xb = d_xpad + (cc * 16 + ci) * PCH + corner;
            float xv[27];
#pragma unroll
            for (int t = 0; t < 27; t++)
                xv[t] = __ldg(xb + TAPOFF(t));
#pragma unroll
            for (int t = 0; t < 27; t++) {
                const ull x2 = pack2(xv[t], xv[t]);
                const ulonglong2 wv =
                    *(const ulonglong2*)&ws[(ci * 27 + t) * 8];
                fma2(acc2[0], x2, wv.x);
                fma2(acc2[1], x2, wv.y);
                const ulonglong2 wv2 =
                    *(const ulonglong2*)&ws[(ci * 27 + t) * 8 + 4];
                fma2(acc2[2], x2, wv2.x);
                fma2(acc2[3], x2, wv2.y);
            }
        }
        __syncthreads();
    }

    const int n = d * (HH * WW) + h * WW + w;
    float* dst = gy == 0 ? d_theta : d_phi;
    const float* bias = gy == 0 ? tb : pb;
#pragma unroll
    for (int j = 0; j < 4; j++) {
        float2 u = unpack2(acc2[j]);
        dst[n * 8 + 2 * j]     = u.x + bias[2 * j];
        dst[n * 8 + 2 * j + 1] = u.y + bias[2 * j + 1];
    }
}

// ---------------- kernel 1b: g conv3d via tf32 mma (values path) -----------
// grid: (384, 2): bx -> (d, h row); gy -> co group of 16. block 96 (3 warps),
// warp wi covers w = wi*8..wi*8+7. A = weights (hi), B = x (hi+lo 2-term).
// smem: wsm 13.8 KB + xs 15.0 KB = 28.8 KB (fits static 48 KB)
__global__ __launch_bounds__(96) void conv_g_mma(
    const float* __restrict__ gw, const float* __restrict__ gb)
{
    __shared__ unsigned wsm[27 * 16 * 8];   // [tap][co16][jpair]
    __shared__ unsigned xs[8 * HALO * 2];   // [ci8][pos][hi,lo] bits

    const int tid = threadIdx.x;
    const int wi = tid / 32, lane = tid % 32;
    const int r = lane / 4, j = lane % 4;
    const int d = blockIdx.x / 24, h = blockIdx.x % 24;
    const int cob = blockIdx.y * 16;

    float dacc[4] = {0.f, 0.f, 0.f, 0.f};

    for (int cc = 0; cc < 8; cc++) {            // 8 chunks of 8 ci (64)
        const int cibase = cc * 8;
        // stage weights (hi only, tf32); jj -> ci = (jj>>1) + (jj&1)*4
        for (int i = tid; i < 27 * 16 * 8; i += 96) {
            const int jj  = i & 7;
            const int co  = (i >> 3) & 15;
            const int tap = i >> 7;
            const int ci  = cibase + (jj >> 1) + (jj & 1) * 4;
            wsm[i] = f2tf32(gw[((cob + co) * 64 + ci) * 27 + tap]);
        }
        // stage x halo (hi/lo split). halo coords: padded [d..d+2][h..h+2][0..25]
        for (int i = tid; i < 8 * HALO; i += 96) {
            const int ci  = i / HALO;
            const int pos = i % HALO;
            const int td = pos / 78, rem = pos % 78;
            const int th = rem / 26, pw = rem % 26;
            const float v = d_xpad[(cibase + ci) * PCH +
                                   (d + td) * PPLN + (h + th) * PROW + pw];
            const unsigned hi = f2tf32(v);
            xs[2 * i]     = hi;
            xs[2 * i + 1] = f2tf32(v - __uint_as_float(hi));
        }
        __syncthreads();

#pragma unroll
        for (int tap = 0; tap < 27; tap++) {
            const int td = tap / 9, th = (tap / 3) % 3, tw = tap % 3;
            const int pos = td * 78 + th * 26 + wi * 8 + r + tw;
            const uint2 b0 = *(const uint2*)&xs[2 * (j * HALO + pos)];
            const uint2 b1 = *(const uint2*)&xs[2 * ((j + 4) * HALO + pos)];
            const uint2 a02 = *(const uint2*)&wsm[(tap * 16 + r) * 8 + 2 * j];
            const uint2 a13 = *(const uint2*)&wsm[(tap * 16 + r + 8) * 8 + 2 * j];
            mma_tf32(dacc, a02.x, a13.x, a02.y, a13.y, b0.x, b1.x);
            mma_tf32(dacc, a02.x, a13.x, a02.y, a13.y, b0.y, b1.y);
        }
        __syncthreads();
    }

    // C: c0=(co r, n 2j) c1=(r, 2j+1) c2=(r+8, 2j) c3=(r+8, 2j+1)
    const int nb = d * (HH * WW) + h * WW + wi * 8;
    d_g[(nb + 2 * j)     * 32 + cob + r]     = dacc[0] + gb[cob + r];
    d_g[(nb + 2 * j + 1) * 32 + cob + r]     = dacc[1] + gb[cob + r];
    d_g[(nb + 2 * j)     * 32 + cob + 8 + r] = dacc[2] + gb[cob + 8 + r];
    d_g[(nb + 2 * j + 1) * 32 + cob + 8 + r] = dacc[3] + gb[cob + 8 + r];
}

// ---------------- kernel 2: attention, full tensor-core QK + PV ------------
// grid: (72, KS), block 256 (8 warps). Warp owns 16 queries. (validated)
__global__ __launch_bounds__(256) void attn_split()
{
    __shared__ __align__(16) uint2    ps2[64 * 8];   // phi {hi,lo} tf32 bits
    __shared__ __align__(16) unsigned gs[64 * 32];   // g tile (tf32 bits)

    const int t = threadIdx.x;
    const int warp = t / 32, lane = t % 32;
    const int r = lane / 4, j = lane % 4;
    const int q0 = blockIdx.x * 128 + warp * 16;
    const int k0 = blockIdx.y * KPS;

    unsigned ah[4], al[4];
    {
        const float v0 = __ldg(&d_theta[(q0 + r) * 8 + j])     * LOG2E;
        const float v1 = __ldg(&d_theta[(q0 + 8 + r) * 8 + j]) * LOG2E;
        const float v2 = __ldg(&d_theta[(q0 + r) * 8 + j + 4]) * LOG2E;
        const float v3 = __ldg(&d_theta[(q0 + 8 + r) * 8 + j + 4]) * LOG2E;
        ah[0] = f2tf32(v0); al[0] = f2tf32(v0 - __uint_as_float(ah[0]));
        ah[1] = f2tf32(v1); al[1] = f2tf32(v1 - __uint_as_float(ah[1]));
        ah[2] = f2tf32(v2); al[2] = f2tf32(v2 - __uint_as_float(ah[2]));
        ah[3] = f2tf32(v3); al[3] = f2tf32(v3 - __uint_as_float(ah[3]));
    }

    float dacc[4][4];
#pragma unroll
    for (int g2 = 0; g2 < 4; g2++)
#pragma unroll
        for (int c = 0; c < 4; c++) dacc[g2][c] = 0.f;
    float lr = 0.f, lr8 = 0.f;

    for (int kt = 0; kt < KPS / 64; kt++) {
        __syncthreads();
        {
            const float2 v = ((const float2*)(d_phi + (k0 + kt * 64) * 8))[t];
            uint2 e0, e1;
            e0.x = f2tf32(v.x); e0.y = f2tf32(v.x - __uint_as_float(e0.x));
            e1.x = f2tf32(v.y); e1.y = f2tf32(v.y - __uint_as_float(e1.x));
            ps2[2 * t]     = e0;
            ps2[2 * t + 1] = e1;
        }
        {
            const float4* src = (const float4*)(d_g + (k0 + kt * 64) * 32);
#pragma unroll
            for (int i = 0; i < 2; i++) {
                float4 v = src[t + i * 256];
                uint4 u;
                u.x = f2tf32(v.x); u.y = f2tf32(v.y);
                u.z = f2tf32(v.z); u.w = f2tf32(v.w);
                ((uint4*)gs)[t + i * 256] = u;
            }
        }
        __syncthreads();

#pragma unroll 2
        for (int sub = 0; sub < 8; sub++) {
            const int kb = sub * 8;
            const uint2 bj  = ps2[(kb + r) * 8 + j];
            const uint2 bj4 = ps2[(kb + r) * 8 + j + 4];

            float c[4] = {0.f, 0.f, 0.f, 0.f};
            mma_tf32(c, ah[0], ah[1], ah[2], ah[3], bj.x, bj4.x);
            mma_tf32(c, ah[0], ah[1], ah[2], ah[3], bj.y, bj4.y);
            mma_tf32(c, al[0], al[1], al[2], al[3], bj.x, bj4.x);

            const float p00 = ex2(c[0] - E2);
            const float p01 = ex2(c[1] - E2);
            const float p10 = ex2(c[2] - E2);
            const float p11 = ex2(c[3] - E2);
            lr  += p00 + p01;
            lr8 += p10 + p11;

            const unsigned a0 = f2tf32(p00), a1 = f2tf32(p10);
            const unsigned a2 = f2tf32(p01), a3 = f2tf32(p11);

            const unsigned* gRow0 = &gs[(kb + 2 * j) * 32 + r];
            const unsigned* gRow1 = &gs[(kb + 2 * j + 1) * 32 + r];
#pragma unroll
            for (int grp = 0; grp < 4; grp++) {
                mma_tf32(dacc[grp], a0, a1, a2, a3,
                         gRow0[grp * 8], gRow1[grp * 8]);
            }
        }
    }

    lr  += __shfl_down_sync(0xffffffffu, lr, 1, 4);
    lr  += __shfl_down_sync(0xffffffffu, lr, 2, 4);
    lr8 += __shfl_down_sync(0xffffffffu, lr8, 1, 4);
    lr8 += __shfl_down_sync(0xffffffffu, lr8, 2, 4);

    const int ks = blockIdx.y;
    if (j == 0) {
        d_pl[ks * NSP + q0 + r]     = lr;
        d_pl[ks * NSP + q0 + 8 + r] = lr8;
    }

    {
        float* baseA = &d_pacc[((size_t)ks * NSP + q0 + r) * 32];
        float* baseB = &d_pacc[((size_t)ks * NSP + q0 + 8 + r) * 32];
#pragma unroll
        for (int grp = 0; grp < 4; grp++) {
            const int ch = grp * 8 + 2 * j;
            *(float2*)&baseA[ch] = make_float2(dacc[grp][0], dacc[grp][1]);
            *(float2*)&baseB[ch] = make_float2(dacc[grp][2], dacc[grp][3]);
        }
    }
}

// ---------------- kernel 3: merge splits, channel-parallel -----------------
__global__ __launch_bounds__(128) void attn_combine()
{
    const int q  = blockIdx.x * 128 + threadIdx.x;
    const int cb = blockIdx.y * 4;

    float l = 0.f;
#pragma unroll
    for (int i = 0; i < KS; i++) l += d_pl[i * NSP + q];

    float a0 = 0.f, a1 = 0.f, a2 = 0.f, a3 = 0.f;
#pragma unroll
    for (int i = 0; i < KS; i++) {
        float4 v = *(const float4*)&d_pacc[((size_t)i * NSP + q) * 32 + cb];
        a0 += v.x; a1 += v.y; a2 += v.z; a3 += v.w;
    }

    const float inv = 1.f / l;
    const int d = q / (HH * WW), r = q % (HH * WW);
    const int pidx = (d + 1) * PPLN + (r / WW + 1) * PROW + (r % WW + 1);
    d_ogpad[(cb + 0) * PCH + pidx] = a0 * inv;
    d_ogpad[(cb + 1) * PCH + pidx] = a1 * inv;
    d_ogpad[(cb + 2) * PCH + pidx] = a2 * inv;
    d_ogpad[(cb + 3) * PCH + pidx] = a3 * inv;
}

// ---------------- kernel 4: o-conv via tf32 mma ----------------------------
// grid: (384, 4): bx -> (d, h), gy -> co group of 16. block 96 (3 warps).
__global__ __launch_bounds__(96) void conv_o_mma(
    const float* __restrict__ ow, const float* __restrict__ ob)
{
    __shared__ unsigned wsm[27 * 16 * 8];
    __shared__ unsigned xs[8 * HALO * 2];

    const int tid = threadIdx.x;
    const int wi = tid / 32, lane = tid % 32;
    const int r = lane / 4, j = lane % 4;
    const int d = blockIdx.x / 24, h = blockIdx.x % 24;
    const int cob = blockIdx.y * 16;

    float dacc[4] = {0.f, 0.f, 0.f, 0.f};

    for (int cc = 0; cc < 4; cc++) {            // 4 chunks of 8 ci (32)
        const int cibase = cc * 8;
        for (int i = tid; i < 27 * 16 * 8; i += 96) {
            const int jj  = i & 7;
            const int co  = (i >> 3) & 15;
            const int tap = i >> 7;
            const int ci  = cibase + (jj >> 1) + (jj & 1) * 4;
            wsm[i] = f2tf32(ow[((cob + co) * 32 + ci) * 27 + tap]);
        }
        for (int i = tid; i < 8 * HALO; i += 96) {
            const int ci  = i / HALO;
            const int pos = i % HALO;
            const int td = pos / 78, rem = pos % 78;
            const int th = rem / 26, pw = rem % 26;
            const float v = d_ogpad[(cibase + ci) * PCH +
                                    (d + td) * PPLN + (h + th) * PROW + pw];
            const unsigned hi = f2tf32(v);
            xs[2 * i]     = hi;
            xs[2 * i + 1] = f2tf32(v - __uint_as_float(hi));
        }
        __syncthreads();

#pragma unroll
        for (int tap = 0; tap < 27; tap++) {
            const int td = tap / 9, th = (tap / 3) % 3, tw = tap % 3;
            const int pos = td * 78 + th * 26 + wi * 8 + r + tw;
            const uint2 b0 = *(const uint2*)&xs[2 * (j * HALO + pos)];
            const uint2 b1 = *(const uint2*)&xs[2 * ((j + 4) * HALO + pos)];
            const uint2 a02 = *(const uint2*)&wsm[(tap * 16 + r) * 8 + 2 * j];
            const uint2 a13 = *(const uint2*)&wsm[(tap * 16 + r + 8) * 8 + 2 * j];
            mma_tf32(dacc, a02.x, a13.x, a02.y, a13.y, b0.x, b1.x);
            mma_tf32(dacc, a02.x, a13.x, a02.y, a13.y, b0.y, b1.y);
        }
        __syncthreads();
    }

    const int nb = d * (HH * WW) + h * WW + wi * 8;
    d_y[(cob + r)     * NSP + nb + 2 * j]     = dacc[0] + ob[cob + r];
    d_y[(cob + r)     * NSP + nb + 2 * j + 1] = dacc[1] + ob[cob + r];
    d_y[(cob + 8 + r) * NSP + nb + 2 * j]     = dacc[2] + ob[cob + 8 + r];
    d_y[(cob + 8 + r) * NSP + nb + 2 * j + 1] = dacc[3] + ob[cob + 8 + r];
}

// ---------------- kernel 5: fused BN stats + apply + residual + relu -------
__global__ __launch_bounds__(512) void bn_final(
    const float* __restrict__ x,
    const float* __restrict__ gamma,
    const float* __restrict__ beta,
    float* __restrict__ out)
{
    const int c = blockIdx.x;
    float s = 0.f, s2 = 0.f;
    const float4* yb = (const float4*)&d_y[c * NSP];
    for (int i = threadIdx.x; i < NSP / 4; i += 512) {
        float4 v = yb[i];
        s  += v.x + v.y + v.z + v.w;
        s2 += v.x * v.x + v.y * v.y + v.z * v.z + v.w * v.w;
    }
#pragma unroll
    for (int o = 16; o > 0; o >>= 1) {
        s  += __shfl_down_sync(0xffffffffu, s,  o);
        s2 += __shfl_down_sync(0xffffffffu, s2, o);
    }
    __shared__ float shs[16], shs2[16];
    __shared__ float sh_mean, sh_rstd;
    const int wid = threadIdx.x / 32, lid = threadIdx.x % 32;
    if (lid == 0) { shs[wid] = s; shs2[wid] = s2; }
    __syncthreads();
    if (threadIdx.x == 0) {
        float ts = 0.f, ts2 = 0.f;
#pragma unroll
        for (int i = 0; i < 16; i++) { ts += shs[i]; ts2 += shs2[i]; }
        const float mean = ts * (1.f / NSP);
        const float var  = ts2 * (1.f / NSP) - mean * mean;
        sh_mean = mean;
        sh_rstd = rsqrtf(var + 1e-5f);
    }
    __syncthreads();

    const float mean = sh_mean;
    const float sc   = sh_rstd * gamma[c];
    const float bs   = beta[c];
    const float4* xb = (const float4*)&x[c * NSP];
    float4* ob4 = (float4*)&out[c * NSP];
    for (int i = threadIdx.x; i < NSP / 4; i += 512) {
        float4 y4 = yb[i];
        float4 x4 = xb[i];
        float4 o4;
        o4.x = x4.x + (y4.x - mean) * sc + bs;
        o4.y = x4.y + (y4.y - mean) * sc + bs;
        o4.z = x4.z + (y4.z - mean) * sc + bs;
        o4.w = x4.w + (y4.w - mean) * sc + bs;
        o4.x = o4.x > 0.f ? o4.x : 0.f;
        o4.y = o4.y > 0.f ? o4.y : 0.f;
        o4.z = o4.z > 0.f ? o4.z : 0.f;
        o4.w = o4.w > 0.f ? o4.w : 0.f;
        ob4[i] = o4;
    }
}

// ---------------- launch ---------------------------------------------------
extern "C" void kernel_launch(void* const* d_in, const int* in_sizes, int n_in,
                              void* d_out, int out_size)
{
    (void)in_sizes; (void)n_in; (void)out_size;
    const float* x  = (const float*)d_in[0];
    const float* tw = (const float*)d_in[1];
    const float* tb = (const float*)d_in[2];
    const float* pw = (const float*)d_in[3];
    const float* pb = (const float*)d_in[4];
    const float* gw = (const float*)d_in[5];
    const float* gb = (const float*)d_in[6];
    const float* ow = (const float*)d_in[7];
    const float* ob = (const float*)d_in[8];
    const float* gamma = (const float*)d_in[9];
    const float* beta  = (const float*)d_in[10];
    float* out = (float*)d_out;

    pad_x<<<(64 * NSP + 255) / 256, 256>>>(x);
    conv_thph<<<dim3(96, 2), 96>>>(tw, tb, pw, pb);
    conv_g_mma<<<dim3(384, 2), 96>>>(gw, gb);
    attn_split<<<dim3(NSP / 128, KS), 256>>>();
    attn_combine<<<dim3(NSP / 128, 8), 128>>>();
    conv_o_mma<<<dim3(384, 4), 96>>>(ow, ob);
    bn_final<<<64, 512>>>(x, gamma, beta, out);
}

// round 17
// speedup vs baseline: 1.6920x; 1.6920x over previous
#include <cuda_runtime.h>
#include <math.h>

#define NSP 9216        // 16*24*24
#define DD 16
#define HH 24
#define WW 24
#define PROW 26         // padded row (W+2)
#define PPLN 676        // padded plane (H+2)*(W+2)
#define PCH  12168      // padded channel (D+2)*PPLN
#define KS 16           // key splits for attention
#define KPS (NSP / KS)  // 576 keys per split
#define ESHIFT 40.0f    // fixed softmax shift
#define LOG2E 1.4426950408889634f
#define E2 (ESHIFT * LOG2E)
#define GSTR 36         // gs row stride (bank-conflict-free padding)
#define PSTR 10         // ps2 row stride in uint2

typedef unsigned long long ull;

// ---------------- f32x2 packed helpers (sm_100+) ---------------------------
__device__ __forceinline__ ull pack2(float lo, float hi) {
    ull r;
    asm("mov.b64 %0, {%1, %2};" : "=l"(r) : "f"(lo), "f"(hi));
    return r;
}
__device__ __forceinline__ float2 unpack2(ull v) {
    float2 f;
    asm("mov.b64 {%0, %1}, %2;" : "=f"(f.x), "=f"(f.y) : "l"(v));
    return f;
}
__device__ __forceinline__ void fma2(ull& d, ull a, ull b) {
    asm("fma.rn.f32x2 %0, %1, %2, %3;" : "=l"(d) : "l"(a), "l"(b), "l"(d));
}
__device__ __forceinline__ unsigned f2tf32(float f) {
    unsigned u;
    asm("cvt.rna.tf32.f32 %0, %1;" : "=r"(u) : "f"(f));
    return u;
}
__device__ __forceinline__ float ex2(float x) {
    float r;
    asm("ex2.approx.f32 %0, %1;" : "=f"(r) : "f"(x));
    return r;
}
// D += A(16x8) @ B(8x8), tf32 inputs, f32 accum (m16n8k8 row.col)
__device__ __forceinline__ void mma_tf32(float* d,
    unsigned a0, unsigned a1, unsigned a2, unsigned a3,
    unsigned b0, unsigned b1) {
    asm("mma.sync.aligned.m16n8k8.row.col.f32.tf32.tf32.f32 "
        "{%0,%1,%2,%3}, {%4,%5,%6,%7}, {%8,%9}, {%0,%1,%2,%3};"
        : "+f"(d[0]), "+f"(d[1]), "+f"(d[2]), "+f"(d[3])
        : "r"(a0), "r"(a1), "r"(a2), "r"(a3), "r"(b0), "r"(b1));
}

// ---------------- scratch (device globals; zero-initialized) ---------------
__device__ __align__(16) float d_xpad[64 * PCH];      // padded x (borders 0)
__device__ __align__(16) float d_ogpad[32 * PCH];     // padded attn out
__device__ __align__(16) float d_theta[NSP * 8];      // [n][c]
__device__ __align__(16) float d_phi[NSP * 8];        // [n][c]
__device__ __align__(16) float d_g[NSP * 32];         // [n][c]
__device__ __align__(16) float d_pl[KS * NSP];        // partial sum
__device__ __align__(16) float d_pacc[KS * NSP * 32]; // partial acc
__device__ __align__(16) float d_y[64 * NSP];         // o-conv out, [c][n]

// tap offsets into padded layout (compile-time immediates after unroll)
#define TAPOFF(t) ((t / 9) * PPLN + ((t / 3) % 3) * PROW + (t % 3))

// ---------------- kernel 0: pad x into halo layout -------------------------
__global__ __launch_bounds__(256) void pad_x(const float* __restrict__ x)
{
    const int idx = blockIdx.x * 256 + threadIdx.x;
    if (idx >= 64 * NSP) return;
    const int c = idx / NSP, n = idx % NSP;
    const int d = n / (HH * WW), r = n % (HH * WW);
    const int h = r / WW, w = r % WW;
    d_xpad[c * PCH + (d + 1) * PPLN + (h + 1) * PROW + (w + 1)] = x[idx];
}

// ---------------- kernel 1: fused theta/phi/g conv3d (round-13 proven) -----
// grid: (96, 6) — 96 spatial tiles (1x4x24), 6 co-groups of 8
__global__ __launch_bounds__(96) void conv_qkv(
    const float* __restrict__ tw, const float* __restrict__ tb,
    const float* __restrict__ pw, const float* __restrict__ pb,
    const float* __restrict__ gw, const float* __restrict__ gb)
{
    __shared__ __align__(16) float ws[16 * 27 * 8];   // [ci][tap][co]

    const int tid = threadIdx.x;
    const int gy = blockIdx.y;
    const int d = blockIdx.x / 6;
    const int h = (blockIdx.x % 6) * 4 + tid / 24;
    const int w = tid % 24;
    const int corner = d * PPLN + h * PROW + w;

    ull acc2[4];
#pragma unroll
    for (int j = 0; j < 4; j++) acc2[j] = 0ull;

    for (int cc = 0; cc < 4; cc++) {          // ci chunks of 16
        for (int i = tid; i < 16 * 27 * 8; i += 96) {
            const int ci  = i / (27 * 8);
            const int rem = i % (27 * 8);
            const int tap = rem / 8;
            const int co  = rem % 8;
            const int cig = cc * 16 + ci;
            float v;
            if (gy == 0)      v = tw[(co * 64 + cig) * 27 + tap];
            else if (gy == 1) v = pw[(co * 64 + cig) * 27 + tap];
            else              v = gw[(((gy - 2) * 8 + co) * 64 + cig) * 27 + tap];
            ws[(ci * 27 + tap) * 8 + co] = v;
        }
        __syncthreads();

        for (int ci = 0; ci < 16; ci++) {
            const float* xb = d_xpad + (cc * 16 + ci) * PCH + corner;
            float xv[27];
#pragma unroll
            for (int t = 0; t < 27; t++)
                xv[t] = __ldg(xb + TAPOFF(t));
#pragma unroll
            for (int t = 0; t < 27; t++) {
                const ull x2 = pack2(xv[t], xv[t]);
                const ulonglong2 wv =
                    *(const ulonglong2*)&ws[(ci * 27 + t) * 8];
                fma2(acc2[0], x2, wv.x);
                fma2(acc2[1], x2, wv.y);
                const ulonglong2 wv2 =
                    *(const ulonglong2*)&ws[(ci * 27 + t) * 8 + 4];
                fma2(acc2[2], x2, wv2.x);
                fma2(acc2[3], x2, wv2.y);
            }
        }
        __syncthreads();
    }

    float acc[8];
#pragma unroll
    for (int j = 0; j < 4; j++) {
        float2 u = unpack2(acc2[j]);
        acc[2 * j] = u.x; acc[2 * j + 1] = u.y;
    }

    const int n = d * (HH * WW) + h * WW + w;
    if (gy == 0) {
#pragma unroll
        for (int c = 0; c < 8; c++) d_theta[n * 8 + c] = acc[c] + tb[c];
    } else if (gy == 1) {
#pragma unroll
        for (int c = 0; c < 8; c++) d_phi[n * 8 + c] = acc[c] + pb[c];
    } else {
        const int cb = (gy - 2) * 8;
#pragma unroll
        for (int c = 0; c < 8; c++)
            d_g[n * 32 + cb + c] = acc[c] + gb[cb + c];
    }
}

// ---------------- kernel 2: attention, tensor-core QK + PV, padded smem ----
// grid: (72, KS), block 256 (8 warps). Warp owns 16 queries.
// gs rows padded to GSTR=36 words: PV B-load bank = (8j + r + 8grp) % 32,
// all 32 lanes distinct -> conflict-free (was 4-way at stride 32).
// ps2 rows padded to PSTR=10 uint2: bank = (20r + 2j) % 32, breaks r-parity.
__global__ __launch_bounds__(256) void attn_split()
{
    __shared__ __align__(16) uint2    ps2[64 * PSTR];  // phi {hi,lo} tf32
    __shared__ __align__(16) unsigned gs[64 * GSTR];   // g tile (tf32 bits)

    const int t = threadIdx.x;
    const int warp = t / 32, lane = t % 32;
    const int r = lane / 4, j = lane % 4;
    const int q0 = blockIdx.x * 128 + warp * 16;
    const int k0 = blockIdx.y * KPS;

    unsigned ah[4], al[4];
    {
        const float v0 = __ldg(&d_theta[(q0 + r) * 8 + j])     * LOG2E;
        const float v1 = __ldg(&d_theta[(q0 + 8 + r) * 8 + j]) * LOG2E;
        const float v2 = __ldg(&d_theta[(q0 + r) * 8 + j + 4]) * LOG2E;
        const float v3 = __ldg(&d_theta[(q0 + 8 + r) * 8 + j + 4]) * LOG2E;
        ah[0] = f2tf32(v0); al[0] = f2tf32(v0 - __uint_as_float(ah[0]));
        ah[1] = f2tf32(v1); al[1] = f2tf32(v1 - __uint_as_float(ah[1]));
        ah[2] = f2tf32(v2); al[2] = f2tf32(v2 - __uint_as_float(ah[2]));
        ah[3] = f2tf32(v3); al[3] = f2tf32(v3 - __uint_as_float(ah[3]));
    }

    float dacc[4][4];
#pragma unroll
    for (int g2 = 0; g2 < 4; g2++)
#pragma unroll
        for (int c = 0; c < 4; c++) dacc[g2][c] = 0.f;
    float lr = 0.f, lr8 = 0.f;

    for (int kt = 0; kt < KPS / 64; kt++) {
        __syncthreads();
        {   // phi: key = t/4, channel pair = 2*(t%4)
            const float2 v = ((const float2*)(d_phi + (k0 + kt * 64) * 8))[t];
            uint2 e0, e1;
            e0.x = f2tf32(v.x); e0.y = f2tf32(v.x - __uint_as_float(e0.x));
            e1.x = f2tf32(v.y); e1.y = f2tf32(v.y - __uint_as_float(e1.x));
            const int key = t / 4, cp = 2 * (t % 4);
            ps2[key * PSTR + cp]     = e0;
            ps2[key * PSTR + cp + 1] = e1;
        }
        {   // g: padded-row store
            const float4* src = (const float4*)(d_g + (k0 + kt * 64) * 32);
#pragma unroll
            for (int i = 0; i < 2; i++) {
                const int idx = t + i * 256;
                float4 v = src[idx];
                const int key = idx / 8, cb = 4 * (idx % 8);
                unsigned* dst = &gs[key * GSTR + cb];
                dst[0] = f2tf32(v.x); dst[1] = f2tf32(v.y);
                dst[2] = f2tf32(v.z); dst[3] = f2tf32(v.w);
            }
        }
        __syncthreads();

#pragma unroll 2
        for (int sub = 0; sub < 8; sub++) {
            const int kb = sub * 8;
            const uint2 bj  = ps2[(kb + r) * PSTR + j];
            const uint2 bj4 = ps2[(kb + r) * PSTR + j + 4];

            float c[4] = {0.f, 0.f, 0.f, 0.f};
            mma_tf32(c, ah[0], ah[1], ah[2], ah[3], bj.x, bj4.x);
            mma_tf32(c, ah[0], ah[1], ah[2], ah[3], bj.y, bj4.y);
            mma_tf32(c, al[0], al[1], al[2], al[3], bj.x, bj4.x);

            const float p00 = ex2(c[0] - E2);
            const float p01 = ex2(c[1] - E2);
            const float p10 = ex2(c[2] - E2);
            const float p11 = ex2(c[3] - E2);
            lr  += p00 + p01;
            lr8 += p10 + p11;

            const unsigned a0 = f2tf32(p00), a1 = f2tf32(p10);
            const unsigned a2 = f2tf32(p01), a3 = f2tf32(p11);

            const unsigned* gRow0 = &gs[(kb + 2 * j) * GSTR + r];
            const unsigned* gRow1 = &gs[(kb + 2 * j + 1) * GSTR + r];
#pragma unroll
            for (int grp = 0; grp < 4; grp++) {
                mma_tf32(dacc[grp], a0, a1, a2, a3,
                         gRow0[grp * 8], gRow1[grp * 8]);
            }
        }
    }

    lr  += __shfl_down_sync(0xffffffffu, lr, 1, 4);
    lr  += __shfl_down_sync(0xffffffffu, lr, 2, 4);
    lr8 += __shfl_down_sync(0xffffffffu, lr8, 1, 4);
    lr8 += __shfl_down_sync(0xffffffffu, lr8, 2, 4);

    const int ks = blockIdx.y;
    if (j == 0) {
        d_pl[ks * NSP + q0 + r]     = lr;
        d_pl[ks * NSP + q0 + 8 + r] = lr8;
    }

    {
        float* baseA = &d_pacc[((size_t)ks * NSP + q0 + r) * 32];
        float* baseB = &d_pacc[((size_t)ks * NSP + q0 + 8 + r) * 32];
#pragma unroll
        for (int grp = 0; grp < 4; grp++) {
            const int ch = grp * 8 + 2 * j;
            *(float2*)&baseA[ch] = make_float2(dacc[grp][0], dacc[grp][1]);
            *(float2*)&baseB[ch] = make_float2(dacc[grp][2], dacc[grp][3]);
        }
    }
}

// ---------------- kernel 3: merge splits, channel-parallel -----------------
// grid: (72, 8), block 128 — each block handles 4 of 32 channels
__global__ __launch_bounds__(128) void attn_combine()
{
    const int q  = blockIdx.x * 128 + threadIdx.x;
    const int cb = blockIdx.y * 4;

    float l = 0.f;
#pragma unroll
    for (int i = 0; i < KS; i++) l += d_pl[i * NSP + q];

    float a0 = 0.f, a1 = 0.f, a2 = 0.f, a3 = 0.f;
#pragma unroll
    for (int i = 0; i < KS; i++) {
        float4 v = *(const float4*)&d_pacc[((size_t)i * NSP + q) * 32 + cb];
        a0 += v.x; a1 += v.y; a2 += v.z; a3 += v.w;
    }

    const float inv = 1.f / l;
    const int d = q / (HH * WW), r = q % (HH * WW);
    const int pidx = (d + 1) * PPLN + (r / WW + 1) * PROW + (r % WW + 1);
    d_ogpad[(cb + 0) * PCH + pidx] = a0 * inv;
    d_ogpad[(cb + 1) * PCH + pidx] = a1 * inv;
    d_ogpad[(cb + 2) * PCH + pidx] = a2 * inv;
    d_ogpad[(cb + 3) * PCH + pidx] = a3 * inv;
}

// ---------------- kernel 4: o-conv scalar (round-13 proven) ----------------
// grid: (96, 8) — 96 spatial tiles, 8 co-groups of 8
__global__ __launch_bounds__(96) void conv_o(
    const float* __restrict__ ow, const float* __restrict__ ob)
{
    __shared__ __align__(16) float ws[16 * 27 * 8];

    const int tid = threadIdx.x;
    const int gy = blockIdx.y;
    const int d = blockIdx.x / 6;
    const int h = (blockIdx.x % 6) * 4 + tid / 24;
    const int w = tid % 24;
    const int corner = d * PPLN + h * PROW + w;

    ull acc2[4];
#pragma unroll
    for (int j = 0; j < 4; j++) acc2[j] = 0ull;

    for (int cc = 0; cc < 2; cc++) {      // ci chunks of 16 (32 total)
        for (int i = tid; i < 16 * 27 * 8; i += 96) {
            const int ci  = i / (27 * 8);
            const int rem = i % (27 * 8);
            const int tap = rem / 8;
            const int co  = rem % 8;
            ws[(ci * 27 + tap) * 8 + co] =
                ow[((gy * 8 + co) * 32 + cc * 16 + ci) * 27 + tap];
        }
        __syncthreads();

        for (int ci = 0; ci < 16; ci++) {
            const float* xb = d_ogpad + (cc * 16 + ci) * PCH + corner;
            float xv[27];
#pragma unroll
            for (int t = 0; t < 27; t++)
                xv[t] = __ldg(xb + TAPOFF(t));
#pragma unroll
            for (int t = 0; t < 27; t++) {
                const ull x2 = pack2(xv[t], xv[t]);
                const ulonglong2 wv =
                    *(const ulonglong2*)&ws[(ci * 27 + t) * 8];
                fma2(acc2[0], x2, wv.x);
                fma2(acc2[1], x2, wv.y);
                const ulonglong2 wv2 =
                    *(const ulonglong2*)&ws[(ci * 27 + t) * 8 + 4];
                fma2(acc2[2], x2, wv2.x);
                fma2(acc2[3], x2, wv2.y);
            }
        }
        __syncthreads();
    }

    const int n = d * (HH * WW) + h * WW + w;
#pragma unroll
    for (int j = 0; j < 4; j++) {
        float2 u = unpack2(acc2[j]);
        d_y[(gy * 8 + 2 * j)     * NSP + n] = u.x + ob[gy * 8 + 2 * j];
        d_y[(gy * 8 + 2 * j + 1) * NSP + n] = u.y + ob[gy * 8 + 2 * j + 1];
    }
}

// ---------------- kernel 5: fused BN stats + apply + residual + relu -------
__global__ __launch_bounds__(512) void bn_final(
    const float* __restrict__ x,
    const float* __restrict__ gamma,
    const float* __restrict__ beta,
    float* __restrict__ out)
{
    const int c = blockIdx.x;
    float s = 0.f, s2 = 0.f;
    const float4* yb = (const float4*)&d_y[c * NSP];
    for (int i = threadIdx.x; i < NSP / 4; i += 512) {
        float4 v = yb[i];
        s  += v.x + v.y + v.z + v.w;
        s2 += v.x * v.x + v.y * v.y + v.z * v.z + v.w * v.w;
    }
#pragma unroll
    for (int o = 16; o > 0; o >>= 1) {
        s  += __shfl_down_sync(0xffffffffu, s,  o);
        s2 += __shfl_down_sync(0xffffffffu, s2, o);
    }
    __shared__ float shs[16], shs2[16];
    __shared__ float sh_mean, sh_rstd;
    const int wid = threadIdx.x / 32, lid = threadIdx.x % 32;
    if (lid == 0) { shs[wid] = s; shs2[wid] = s2; }
    __syncthreads();
    if (threadIdx.x == 0) {
        float ts = 0.f, ts2 = 0.f;
#pragma unroll
        for (int i = 0; i < 16; i++) { ts += shs[i]; ts2 += shs2[i]; }
        const float mean = ts * (1.f / NSP);
        const float var  = ts2 * (1.f / NSP) - mean * mean;
        sh_mean = mean;
        sh_rstd = rsqrtf(var + 1e-5f);
    }
    __syncthreads();

    const float mean = sh_mean;
    const float sc   = sh_rstd * gamma[c];
    const float bs   = beta[c];
    const float4* xb = (const float4*)&x[c * NSP];
    float4* ob4 = (float4*)&out[c * NSP];
    for (int i = threadIdx.x; i < NSP / 4; i += 512) {
        float4 y4 = yb[i];
        float4 x4 = xb[i];
        float4 o4;
        o4.x = x4.x + (y4.x - mean) * sc + bs;
        o4.y = x4.y + (y4.y - mean) * sc + bs;
        o4.z = x4.z + (y4.z - mean) * sc + bs;
        o4.w = x4.w + (y4.w - mean) * sc + bs;
        o4.x = o4.x > 0.f ? o4.x : 0.f;
        o4.y = o4.y > 0.f ? o4.y : 0.f;
        o4.z = o4.z > 0.f ? o4.z : 0.f;
        o4.w = o4.w > 0.f ? o4.w : 0.f;
        ob4[i] = o4;
    }
}

// ---------------- launch ---------------------------------------------------
extern "C" void kernel_launch(void* const* d_in, const int* in_sizes, int n_in,
                              void* d_out, int out_size)
{
    (void)in_sizes; (void)n_in; (void)out_size;
    const float* x  = (const float*)d_in[0];
    const float* tw = (const float*)d_in[1];
    const float* tb = (const float*)d_in[2];
    const float* pw = (const float*)d_in[3];
    const float* pb = (const float*)d_in[4];
    const float* gw = (const float*)d_in[5];
    const float* gb = (const float*)d_in[6];
    const float* ow = (const float*)d_in[7];
    const float* ob = (const float*)d_in[8];
    const float* gamma = (const float*)d_in[9];
    const float* beta  = (const float*)d_in[10];
    float* out = (float*)d_out;

    pad_x<<<(64 * NSP + 255) / 256, 256>>>(x);
    conv_qkv<<<dim3(96, 6), 96>>>(tw, tb, pw, pb, gw, gb);
    attn_split<<<dim3(NSP / 128, KS), 256>>>();
    attn_combine<<<dim3(NSP / 128, 8), 128>>>();
    conv_o<<<dim3(96, 8), 96>>>(ow, ob);
    bn_final<<<64, 512>>>(x, gamma, beta, out);
}